// round 15
// baseline (speedup 1.0000x reference)
#include <cuda_runtime.h>
#include <cuda_fp16.h>
#include <cuda_bf16.h>
#include <cstdint>

// ---------------------------------------------------------------------------
// Relative attention — fp16 mma.sync m16n8k16 + ldmatrix. Round 15:
//  * GEMMs rebalanced: 4 warps/block, 64x64 warp tiles (32 mma : 8 ldsm per
//    k16 step), 2 blocks/SM — register file no longer the occupancy cap.
//  * flash unchanged (known-good).
// ---------------------------------------------------------------------------

namespace {
constexpr int BATCH = 32;
constexpr int NH    = 8;
constexpr int NTOK  = 577;
constexpr int DIM   = 512;
constexpr int DH    = 64;
constexpr int BH    = BATCH * NH;        // 256
constexpr int MROWS = BATCH * NTOK;      // 18464
constexpr int BPAD  = 640;               // padded bias row stride (bf16)
constexpr int VP    = 640;               // padded V^T row stride (tokens)
constexpr float LOG2E = 1.4426950408889634f;
}

// Scratch (device globals: allocation-free contract; zero-initialized)
__device__ __half g_xh[MROWS * DIM];                   // fp16 x
__device__ __half g_wqh[3 * DIM * DIM];                // fp16 qkv_w
__device__ __half g_wph[DIM * DIM];                    // fp16 proj_w
__device__ __half g_qh[BH * NTOK * DH];                // fp16 Q (pre-scaled x0.125)
__device__ __half g_kh[BH * NTOK * DH];                // fp16 K
__device__ __half g_vth[BH * DH * VP];                 // fp16 V^T, pads stay 0
__device__ __nv_bfloat16 g_biasph[NH * NTOK * BPAD];   // bf16 bias, pad=-1e30
__device__ __half g_attnh[MROWS * DIM];                // fp16 attention out

// ---------------------------------------------------------------------------
__device__ __forceinline__ void mma16(float* d, const uint32_t* a, const uint32_t* b) {
    asm volatile(
        "mma.sync.aligned.m16n8k16.row.col.f32.f16.f16.f32 "
        "{%0,%1,%2,%3},{%4,%5,%6,%7},{%8,%9},{%0,%1,%2,%3};"
        : "+f"(d[0]), "+f"(d[1]), "+f"(d[2]), "+f"(d[3])
        : "r"(a[0]), "r"(a[1]), "r"(a[2]), "r"(a[3]),
          "r"(b[0]), "r"(b[1]));
}

__device__ __forceinline__ void ldsm4(uint32_t* r, uint32_t addr) {
    asm volatile("ldmatrix.sync.aligned.m8n8.x4.shared.b16 {%0,%1,%2,%3}, [%4];"
                 : "=r"(r[0]), "=r"(r[1]), "=r"(r[2]), "=r"(r[3]) : "r"(addr));
}

__device__ __forceinline__ void cp16(void* dst, const void* src) {
    unsigned d = (unsigned)__cvta_generic_to_shared(dst);
    asm volatile("cp.async.cg.shared.global [%0], [%1], 16;\n" :: "r"(d), "l"(src));
}
__device__ __forceinline__ void cp_commit() {
    asm volatile("cp.async.commit_group;\n" ::);
}
template <int N>
__device__ __forceinline__ void cp_wait() {
    asm volatile("cp.async.wait_group %0;\n" :: "n"(N));
}

// ---------------------------------------------------------------------------
// Fused prep: fp16-convert x, qkv_w, proj_w (8 floats/thread); expand bias.
// ---------------------------------------------------------------------------
namespace {
constexpr int N_XH = MROWS * DIM / 8;        // 1181696
constexpr int N_WQ = 3 * DIM * DIM / 8;      // 98304
constexpr int N_WP = DIM * DIM / 8;          // 32768
constexpr int N_B  = NTOK * BPAD;            // 369280
constexpr int N_PREP = N_XH + N_WQ + N_WP + N_B;
}

__device__ __forceinline__ void cvt8(__half* dst, const float4* src, int i) {
    float4 a = src[2 * i], b = src[2 * i + 1];
    __half2* d2 = reinterpret_cast<__half2*>(dst + 8 * i);
    d2[0] = __floats2half2_rn(a.x, a.y);
    d2[1] = __floats2half2_rn(a.z, a.w);
    d2[2] = __floats2half2_rn(b.x, b.y);
    d2[3] = __floats2half2_rn(b.z, b.w);
}

__global__ void prep_all(const float4* __restrict__ x,
                         const float4* __restrict__ wq,
                         const float4* __restrict__ wp,
                         const float* __restrict__ table,
                         const int* __restrict__ rel) {
    int i = blockIdx.x * 256 + threadIdx.x;
    if (i < N_XH) { cvt8(g_xh, x, i); return; }
    i -= N_XH;
    if (i < N_WQ) { cvt8(g_wqh, wq, i); return; }
    i -= N_WQ;
    if (i < N_WP) { cvt8(g_wph, wp, i); return; }
    i -= N_WP;
    if (i < N_B) {
        int n = i / BPAD, c = i - n * BPAD;
        if (c < NTOK) {
            int r = rel[n * NTOK + c];
#pragma unroll
            for (int h = 0; h < NH; ++h)
                g_biasph[((size_t)h * NTOK + n) * BPAD + c] =
                    __float2bfloat16_rn(table[r * NH + h]);
        } else {
            __nv_bfloat16 neg = __float2bfloat16_rn(-1e30f);
#pragma unroll
            for (int h = 0; h < NH; ++h)
                g_biasph[((size_t)h * NTOK + n) * BPAD + c] = neg;
        }
    }
}

// ---------------------------------------------------------------------------
// fp16 NT GEMM. Block tile 128x128, 4 warps (128 thr), 64x64 warp tiles.
// 64-K chunks, 3-stage cp.async ring, one sync per iter, 2 blocks/SM.
// Rows padded to 72 halves (144 B). MODE 0: q(x0.125)/k scatter + V smem
// transpose -> g_vth.  MODE 1: f32 acc + bias -> Cout.
// ---------------------------------------------------------------------------
namespace {
constexpr int ST_B   = 2 * 128 * 144;               // bytes per stage (A+B)
constexpr int NSTG   = 3;
constexpr int NCHUNK = DIM / 64;                    // 8
constexpr int GEMM_SMEM = NSTG * ST_B;              // 110592 bytes
}

template <int MODE>
__global__ __launch_bounds__(128, 2) void gemm_fp16(const __half* __restrict__ A,
                                                    const __half* __restrict__ Bm,
                                                    const float* __restrict__ bias,
                                                    float* __restrict__ Cout) {
    extern __shared__ char smc[];
    const int tid = threadIdx.x;
    const int lane = tid & 31, wid = tid >> 5;
    const int g = lane >> 2, t = lane & 3;
    const int m0 = blockIdx.y * 128, n0 = blockIdx.x * 128;
    const int wm = (wid >> 1) * 64, wn = (wid & 1) * 64;
    const uint32_t sb = (uint32_t)__cvta_generic_to_shared(smc);

    const uint32_t laneA = (uint32_t)((((lane >> 3) & 1) * 8 + (lane & 7)) * 144
                                      + (lane >> 4) * 16);
    const uint32_t laneB = (uint32_t)((((lane >> 4) & 1) * 8 + (lane & 7)) * 144
                                      + ((lane >> 3) & 1) * 16);

    float acc[4][8][4];
#pragma unroll
    for (int i = 0; i < 4; ++i)
#pragma unroll
        for (int j = 0; j < 8; ++j)
#pragma unroll
            for (int e = 0; e < 4; ++e) acc[i][j][e] = 0.f;

    auto issue = [&](int c) {
        if (c < NCHUNK) {
            const int st = c % NSTG;
            const int k0 = c * 64;
            char* As = smc + st * ST_B;
            char* Bs = As + 128 * 144;
#pragma unroll
            for (int it = 0; it < 16; ++it) {
                int v = tid + it * 128;
                int row = v >> 3, c8 = (v & 7) * 8;        // halves
                if (row < 128) {                           // warp-uniform per it
                    int gm = m0 + row; if (gm > MROWS - 1) gm = MROWS - 1;
                    cp16(As + row * 144 + c8 * 2, A + (size_t)gm * DIM + k0 + c8);
                } else {
                    int r2 = row - 128;
                    int gn = n0 + r2;
                    cp16(Bs + r2 * 144 + c8 * 2, Bm + (size_t)gn * DIM + k0 + c8);
                }
            }
        }
        cp_commit();
    };

    issue(0); issue(1);
    for (int c = 0; c < NCHUNK; ++c) {
        cp_wait<1>();
        __syncthreads();
        issue(c + 2);

        const int st = c % NSTG;
        const uint32_t aAddr = sb + st * ST_B + wm * 144 + laneA;
        const uint32_t bAddr = sb + st * ST_B + 128 * 144 + wn * 144 + laneB;
#pragma unroll
        for (int ks = 0; ks < 4; ++ks) {
            const uint32_t kd = ks * 32;
            uint32_t aR[4][4];
#pragma unroll
            for (int mf = 0; mf < 4; ++mf)
                ldsm4(aR[mf], aAddr + mf * (16 * 144) + kd);
            uint32_t bR[4][4];
#pragma unroll
            for (int p = 0; p < 4; ++p)
                ldsm4(bR[p], bAddr + p * (16 * 144) + kd);
#pragma unroll
            for (int p = 0; p < 4; ++p)
#pragma unroll
                for (int s = 0; s < 2; ++s) {
                    const int nf = p * 2 + s;
#pragma unroll
                    for (int mf = 0; mf < 4; ++mf)
                        mma16(acc[mf][nf], aR[mf], &bR[p][2 * s]);
                }
        }
    }
    __syncthreads();

    if (MODE == 0) {
        if (n0 >= 1024) {
            // ---- V block: transpose 128x128 via smem, coalesced g_vth ----
            float* Ts = reinterpret_cast<float*>(smc);    // [128][132] f32
#pragma unroll
            for (int mf = 0; mf < 4; ++mf)
#pragma unroll
                for (int ri = 0; ri < 2; ++ri) {
                    int lr = wm + mf * 16 + g + ri * 8;
#pragma unroll
                    for (int nf = 0; nf < 8; ++nf)
#pragma unroll
                        for (int ci = 0; ci < 2; ++ci) {
                            int lc = wn + nf * 8 + t * 2 + ci;
                            Ts[lc * 132 + lr] = acc[mf][nf][ri * 2 + ci];
                        }
                }
            __syncthreads();
#pragma unroll 8
            for (int cc = 0; cc < 32; ++cc) {
                int lc = wid * 32 + cc;
                int gn = n0 + lc;
                int rem = gn & 511;
                int h_ = rem >> 6, dd = rem & 63;
#pragma unroll
                for (int mi = 0; mi < 4; ++mi) {
                    int lr = mi * 32 + lane;
                    int gm = m0 + lr;
                    if (gm < MROWS) {
                        int b_ = gm / NTOK;
                        int n_ = gm - b_ * NTOK;
                        g_vth[(((size_t)(b_ * NH + h_)) * DH + dd) * VP + n_] =
                            __float2half_rn(Ts[lc * 132 + lr]);
                    }
                }
            }
        } else {
            // ---- Q/K blocks: half2 scatter; Q pre-scaled by 0.125 (exact) ----
#pragma unroll
            for (int mf = 0; mf < 4; ++mf) {
#pragma unroll
                for (int ri = 0; ri < 2; ++ri) {
                    int gm = m0 + wm + mf * 16 + g + ri * 8;
                    if (gm >= MROWS) continue;
                    int b_ = gm / NTOK;
                    int n_ = gm - b_ * NTOK;
#pragma unroll
                    for (int nf = 0; nf < 8; ++nf) {
                        int gn = n0 + wn + nf * 8 + t * 2;
                        int part = gn >> 9;
                        int rem = gn & 511;
                        int h_ = rem >> 6;
                        int dd = rem & 63;
                        float s = (part == 0) ? 0.125f : 1.f;
                        __half2 hv = __floats2half2_rn(acc[mf][nf][ri * 2] * s,
                                                       acc[mf][nf][ri * 2 + 1] * s);
                        __half* dst = (part == 0) ? g_qh : g_kh;
                        *reinterpret_cast<__half2*>(
                            dst + ((size_t)(b_ * NH + h_) * NTOK + n_) * DH + dd) = hv;
                    }
                }
            }
        }
    } else {
#pragma unroll
        for (int mf = 0; mf < 4; ++mf) {
#pragma unroll
            for (int ri = 0; ri < 2; ++ri) {
                int gm = m0 + wm + mf * 16 + g + ri * 8;
                if (gm >= MROWS) continue;
#pragma unroll
                for (int nf = 0; nf < 8; ++nf) {
                    int cbase = n0 + wn + nf * 8 + t * 2;
                    float2 o;
                    o.x = acc[mf][nf][ri * 2 + 0] + bias[cbase];
                    o.y = acc[mf][nf][ri * 2 + 1] + bias[cbase + 1];
                    *reinterpret_cast<float2*>(Cout + (size_t)gm * DIM + cbase) = o;
                }
            }
        }
    }
}

// ---------------------------------------------------------------------------
// Fused flash attention (unchanged from round 14).
// ---------------------------------------------------------------------------
namespace {
constexpr int KSB = 0;                          // bytes
constexpr int VSB = KSB + 2 * 64 * 144;         // 18432
constexpr int BBB = VSB + 2 * 64 * 144;         // 36864
constexpr int FL_SMEM = BBB + 2 * 128 * 144;    // 73728 bytes
}

__global__ __launch_bounds__(256, 2) void flash_attn() {
    extern __shared__ char smc[];
    const uint32_t sb = (uint32_t)__cvta_generic_to_shared(smc);

    const int bh = blockIdx.y, qt = blockIdx.x;
    const int tid = threadIdx.x;
    const int wid = tid >> 5, lane = tid & 31;
    const int g = lane >> 2, t = lane & 3;
    const __half* qb = g_qh + (size_t)bh * NTOK * DH;
    const __half* kb = g_kh + (size_t)bh * NTOK * DH;
    const __half* vtb = g_vth + (size_t)bh * DH * VP;
    const __nv_bfloat16* bp = g_biasph + (size_t)(bh & 7) * NTOK * BPAD;

    const uint32_t laneB = (uint32_t)((((lane >> 4) & 1) * 8 + (lane & 7)) * 144
                                      + ((lane >> 3) & 1) * 16);

    auto issueTile = [&](int st, int kt) {
        const int k0 = kt * 64;
        char* Ks = smc + KSB + st * (64 * 144);
        char* Vt = smc + VSB + st * (64 * 144);
        char* Bs = smc + BBB + st * (128 * 144);
#pragma unroll
        for (int it = 0; it < 4; ++it) {            // bias: 128 rows x 8 chunks
            int v = tid + it * 256;
            int row = v >> 3, c8 = (v & 7) * 8;
            int gq = qt * 128 + row; if (gq > NTOK - 1) gq = NTOK - 1;
            cp16(Bs + row * 144 + c8 * 2, bp + (size_t)gq * BPAD + k0 + c8);
        }
#pragma unroll
        for (int it = 0; it < 2; ++it) {            // K: 64 rows x 8 chunks
            int v = tid + it * 256;
            int row = v >> 3, c8 = (v & 7) * 8;
            int gk = k0 + row; if (gk > NTOK - 1) gk = NTOK - 1;  // bias pad masks
            cp16(Ks + row * 144 + c8 * 2, kb + (size_t)gk * DH + c8);
        }
#pragma unroll
        for (int it = 0; it < 2; ++it) {            // V^T: 64 d-rows x 8 chunks
            int v = tid + it * 256;
            int row = v >> 3, c8 = (v & 7) * 8;
            cp16(Vt + row * 144 + c8 * 2, vtb + (size_t)row * VP + k0 + c8);
        }
        cp_commit();
    };

    issueTile(0, 0);

    const int q0 = wid * 16;
    const int rowA = qt * 128 + q0 + g;
    const int rowB = rowA + 8;

    const __half2* qA = reinterpret_cast<const __half2*>(
        qb + (size_t)min(rowA, NTOK - 1) * DH);
    const __half2* qB = reinterpret_cast<const __half2*>(
        qb + (size_t)min(rowB, NTOK - 1) * DH);
    uint32_t qf[4][4];
#pragma unroll
    for (int ks = 0; ks < 4; ++ks) {
        qf[ks][0] = *reinterpret_cast<const uint32_t*>(qA + ks * 8 + t);
        qf[ks][1] = *reinterpret_cast<const uint32_t*>(qB + ks * 8 + t);
        qf[ks][2] = *reinterpret_cast<const uint32_t*>(qA + ks * 8 + t + 4);
        qf[ks][3] = *reinterpret_cast<const uint32_t*>(qB + ks * 8 + t + 4);
    }

    float accO[8][4];
#pragma unroll
    for (int df = 0; df < 8; ++df)
#pragma unroll
        for (int e = 0; e < 4; ++e) accO[df][e] = 0.f;
    float m_a = -1e30f, m_b = -1e30f, sum_a = 0.f, sum_b = 0.f;

    for (int kt = 0; kt < 10; ++kt) {
        const int st = kt & 1;
        const uint32_t ksAddr = sb + KSB + st * (64 * 144) + laneB;
        const uint32_t vtAddr = sb + VSB + st * (64 * 144) + laneB;
        const __nv_bfloat16* Bs =
            reinterpret_cast<const __nv_bfloat16*>(smc + BBB + st * (128 * 144));

        if (kt < 9) { issueTile(st ^ 1, kt + 1); cp_wait<1>(); }
        else cp_wait<0>();
        __syncthreads();

        // S initialized with bias (bf16 -> f32); QK mma accumulates on top.
        float S[8][4];
#pragma unroll
        for (int nf = 0; nf < 8; ++nf) {
            int c = nf * 8 + t * 2;
            float2 bA = __bfloat1622float2(
                *reinterpret_cast<const __nv_bfloat162*>(&Bs[(q0 + g) * 72 + c]));
            float2 bB = __bfloat1622float2(
                *reinterpret_cast<const __nv_bfloat162*>(&Bs[(q0 + g + 8) * 72 + c]));
            S[nf][0] = bA.x; S[nf][1] = bA.y;
            S[nf][2] = bB.x; S[nf][3] = bB.y;
        }
#pragma unroll
        for (int ks = 0; ks < 4; ++ks) {
            const uint32_t kd = ks * 32;
#pragma unroll
            for (int p = 0; p < 4; ++p) {
                uint32_t bR[4];
                ldsm4(bR, ksAddr + p * (16 * 144) + kd);
                mma16(S[p * 2 + 0], qf[ks], &bR[0]);
                mma16(S[p * 2 + 1], qf[ks], &bR[2]);
            }
        }

        // online softmax (Q pre-scaled: S is already the full logit)
        float ma = -1e30f, mb = -1e30f;
#pragma unroll
        for (int nf = 0; nf < 8; ++nf) {
            ma = fmaxf(ma, fmaxf(S[nf][0], S[nf][1]));
            mb = fmaxf(mb, fmaxf(S[nf][2], S[nf][3]));
        }
        ma = fmaxf(ma, __shfl_xor_sync(0xFFFFFFFFu, ma, 1));
        ma = fmaxf(ma, __shfl_xor_sync(0xFFFFFFFFu, ma, 2));
        mb = fmaxf(mb, __shfl_xor_sync(0xFFFFFFFFu, mb, 1));
        mb = fmaxf(mb, __shfl_xor_sync(0xFFFFFFFFu, mb, 2));

        float mna = fmaxf(m_a, ma), mnb = fmaxf(m_b, mb);
        float alA = exp2f((m_a - mna) * LOG2E);
        float alB = exp2f((m_b - mnb) * LOG2E);
        m_a = mna; m_b = mnb;

        // P = 2^((S-m)*log2e) computed in f16x2 (ex2.approx.f16x2)
        uint32_t Sp[8][2];
        float pa = 0.f, pb = 0.f;
#pragma unroll
        for (int nf = 0; nf < 8; ++nf) {
            __half2 e0 = h2exp2(__floats2half2_rn((S[nf][0] - mna) * LOG2E,
                                                  (S[nf][1] - mna) * LOG2E));
            __half2 e1 = h2exp2(__floats2half2_rn((S[nf][2] - mnb) * LOG2E,
                                                  (S[nf][3] - mnb) * LOG2E));
            Sp[nf][0] = *reinterpret_cast<uint32_t*>(&e0);
            Sp[nf][1] = *reinterpret_cast<uint32_t*>(&e1);
            float2 f0 = __half22float2(e0);
            float2 f1 = __half22float2(e1);
            pa += f0.x + f0.y;
            pb += f1.x + f1.y;
        }
        sum_a = sum_a * alA + pa;
        sum_b = sum_b * alB + pb;
#pragma unroll
        for (int df = 0; df < 8; ++df) {
            accO[df][0] *= alA; accO[df][1] *= alA;
            accO[df][2] *= alB; accO[df][3] *= alB;
        }

        // O += P V : a-fragments from packed P, b from V^T ldmatrix
#pragma unroll
        for (int ks = 0; ks < 4; ++ks) {
            uint32_t a[4];
            a[0] = Sp[2 * ks][0];
            a[1] = Sp[2 * ks][1];
            a[2] = Sp[2 * ks + 1][0];
            a[3] = Sp[2 * ks + 1][1];
            const uint32_t kd = ks * 32;
#pragma unroll
            for (int p = 0; p < 4; ++p) {
                uint32_t bR[4];
                ldsm4(bR, vtAddr + p * (16 * 144) + kd);
                mma16(accO[p * 2 + 0], a, &bR[0]);
                mma16(accO[p * 2 + 1], a, &bR[2]);
            }
        }
        __syncthreads();
    }

    sum_a += __shfl_xor_sync(0xFFFFFFFFu, sum_a, 1);
    sum_a += __shfl_xor_sync(0xFFFFFFFFu, sum_a, 2);
    sum_b += __shfl_xor_sync(0xFFFFFFFFu, sum_b, 1);
    sum_b += __shfl_xor_sync(0xFFFFFFFFu, sum_b, 2);
    const float ia = 1.f / sum_a, ib = 1.f / sum_b;

    const int b_ = bh >> 3, h_ = bh & 7;
#pragma unroll
    for (int df = 0; df < 8; ++df) {
        int col = h_ * 64 + df * 8 + t * 2;
        if (rowA < NTOK) {
            __half2 o = __floats2half2_rn(accO[df][0] * ia, accO[df][1] * ia);
            *reinterpret_cast<__half2*>(
                g_attnh + (size_t)(b_ * NTOK + rowA) * DIM + col) = o;
        }
        if (rowB < NTOK) {
            __half2 o = __floats2half2_rn(accO[df][2] * ib, accO[df][3] * ib);
            *reinterpret_cast<__half2*>(
                g_attnh + (size_t)(b_ * NTOK + rowB) * DIM + col) = o;
        }
    }
}

// ---------------------------------------------------------------------------
extern "C" void kernel_launch(void* const* d_in, const int* in_sizes, int n_in,
                              void* d_out, int out_size) {
    (void)in_sizes; (void)n_in; (void)out_size;
    const float* x          = (const float*)d_in[0];
    const float* qkv_w      = (const float*)d_in[1];
    const float* proj_w     = (const float*)d_in[2];
    const float* proj_b     = (const float*)d_in[3];
    const float* bias_table = (const float*)d_in[4];
    const int*   rel_index  = (const int*)d_in[5];
    float* out = (float*)d_out;

    static bool attr_done = false;
    if (!attr_done) {
        cudaFuncSetAttribute(gemm_fp16<0>, cudaFuncAttributeMaxDynamicSharedMemorySize, GEMM_SMEM);
        cudaFuncSetAttribute(gemm_fp16<1>, cudaFuncAttributeMaxDynamicSharedMemorySize, GEMM_SMEM);
        cudaFuncSetAttribute(flash_attn, cudaFuncAttributeMaxDynamicSharedMemorySize, FL_SMEM);
        attr_done = true;
    }

    __half *xh = nullptr, *wqh = nullptr, *wph = nullptr, *ath = nullptr;
    cudaGetSymbolAddress((void**)&xh, g_xh);
    cudaGetSymbolAddress((void**)&wqh, g_wqh);
    cudaGetSymbolAddress((void**)&wph, g_wph);
    cudaGetSymbolAddress((void**)&ath, g_attnh);

    prep_all<<<(N_PREP + 255) / 256, 256>>>(
        (const float4*)x, (const float4*)qkv_w, (const float4*)proj_w,
        bias_table, rel_index);

    gemm_fp16<0><<<dim3(12, 145), 128, GEMM_SMEM>>>(xh, wqh, nullptr, nullptr);
    flash_attn<<<dim3(5, BH), 256, FL_SMEM>>>();
    gemm_fp16<1><<<dim3(4, 145), 128, GEMM_SMEM>>>(ath, wph, proj_b, out);
}

// round 16
// speedup vs baseline: 1.0151x; 1.0151x over previous
#include <cuda_runtime.h>
#include <cuda_fp16.h>
#include <cuda_bf16.h>
#include <cstdint>

// ---------------------------------------------------------------------------
// Relative attention — fp16 mma.sync m16n8k16 + ldmatrix. Round 16:
//  * GEMMs reverted to round-14 config (256 thr, 64x32 warp tiles, 2 blk/SM)
//  * flash: 3-stage ring (ONE sync per kt) + bias S-init via ldmatrix
// ---------------------------------------------------------------------------

namespace {
constexpr int BATCH = 32;
constexpr int NH    = 8;
constexpr int NTOK  = 577;
constexpr int DIM   = 512;
constexpr int DH    = 64;
constexpr int BH    = BATCH * NH;        // 256
constexpr int MROWS = BATCH * NTOK;      // 18464
constexpr int BPAD  = 640;               // padded bias row stride (bf16)
constexpr int VP    = 640;               // padded V^T row stride (tokens)
constexpr float LOG2E = 1.4426950408889634f;
}

// Scratch (device globals: allocation-free contract; zero-initialized)
__device__ __half g_xh[MROWS * DIM];                   // fp16 x
__device__ __half g_wqh[3 * DIM * DIM];                // fp16 qkv_w
__device__ __half g_wph[DIM * DIM];                    // fp16 proj_w
__device__ __half g_qh[BH * NTOK * DH];                // fp16 Q (pre-scaled x0.125)
__device__ __half g_kh[BH * NTOK * DH];                // fp16 K
__device__ __half g_vth[BH * DH * VP];                 // fp16 V^T, pads stay 0
__device__ __nv_bfloat16 g_biasph[NH * NTOK * BPAD];   // bf16 bias, pad=-1e30
__device__ __half g_attnh[MROWS * DIM];                // fp16 attention out

// ---------------------------------------------------------------------------
__device__ __forceinline__ void mma16(float* d, const uint32_t* a, const uint32_t* b) {
    asm volatile(
        "mma.sync.aligned.m16n8k16.row.col.f32.f16.f16.f32 "
        "{%0,%1,%2,%3},{%4,%5,%6,%7},{%8,%9},{%0,%1,%2,%3};"
        : "+f"(d[0]), "+f"(d[1]), "+f"(d[2]), "+f"(d[3])
        : "r"(a[0]), "r"(a[1]), "r"(a[2]), "r"(a[3]),
          "r"(b[0]), "r"(b[1]));
}

__device__ __forceinline__ void ldsm4(uint32_t* r, uint32_t addr) {
    asm volatile("ldmatrix.sync.aligned.m8n8.x4.shared.b16 {%0,%1,%2,%3}, [%4];"
                 : "=r"(r[0]), "=r"(r[1]), "=r"(r[2]), "=r"(r[3]) : "r"(addr));
}

__device__ __forceinline__ void cp16(void* dst, const void* src) {
    unsigned d = (unsigned)__cvta_generic_to_shared(dst);
    asm volatile("cp.async.cg.shared.global [%0], [%1], 16;\n" :: "r"(d), "l"(src));
}
__device__ __forceinline__ void cp_commit() {
    asm volatile("cp.async.commit_group;\n" ::);
}
template <int N>
__device__ __forceinline__ void cp_wait() {
    asm volatile("cp.async.wait_group %0;\n" :: "n"(N));
}

// ---------------------------------------------------------------------------
// Fused prep: fp16-convert x, qkv_w, proj_w (8 floats/thread); expand bias.
// ---------------------------------------------------------------------------
namespace {
constexpr int N_XH = MROWS * DIM / 8;        // 1181696
constexpr int N_WQ = 3 * DIM * DIM / 8;      // 98304
constexpr int N_WP = DIM * DIM / 8;          // 32768
constexpr int N_B  = NTOK * BPAD;            // 369280
constexpr int N_PREP = N_XH + N_WQ + N_WP + N_B;
}

__device__ __forceinline__ void cvt8(__half* dst, const float4* src, int i) {
    float4 a = src[2 * i], b = src[2 * i + 1];
    __half2* d2 = reinterpret_cast<__half2*>(dst + 8 * i);
    d2[0] = __floats2half2_rn(a.x, a.y);
    d2[1] = __floats2half2_rn(a.z, a.w);
    d2[2] = __floats2half2_rn(b.x, b.y);
    d2[3] = __floats2half2_rn(b.z, b.w);
}

__global__ void prep_all(const float4* __restrict__ x,
                         const float4* __restrict__ wq,
                         const float4* __restrict__ wp,
                         const float* __restrict__ table,
                         const int* __restrict__ rel) {
    int i = blockIdx.x * 256 + threadIdx.x;
    if (i < N_XH) { cvt8(g_xh, x, i); return; }
    i -= N_XH;
    if (i < N_WQ) { cvt8(g_wqh, wq, i); return; }
    i -= N_WQ;
    if (i < N_WP) { cvt8(g_wph, wp, i); return; }
    i -= N_WP;
    if (i < N_B) {
        int n = i / BPAD, c = i - n * BPAD;
        if (c < NTOK) {
            int r = rel[n * NTOK + c];
#pragma unroll
            for (int h = 0; h < NH; ++h)
                g_biasph[((size_t)h * NTOK + n) * BPAD + c] =
                    __float2bfloat16_rn(table[r * NH + h]);
        } else {
            __nv_bfloat16 neg = __float2bfloat16_rn(-1e30f);
#pragma unroll
            for (int h = 0; h < NH; ++h)
                g_biasph[((size_t)h * NTOK + n) * BPAD + c] = neg;
        }
    }
}

// ---------------------------------------------------------------------------
// fp16 NT GEMM (round-14 config). Block 128x128, 8 warps, 64x32 warp tiles,
// 64-K chunks, 3-stage cp.async ring, one sync/iter, 2 blocks/SM.
// Rows padded to 72 halves (144 B). MODE 0: q(x0.125)/k scatter + V smem
// transpose -> g_vth.  MODE 1: f32 acc + bias -> Cout.
// ---------------------------------------------------------------------------
namespace {
constexpr int ST_B   = 2 * 128 * 144;               // bytes per stage (A+B)
constexpr int NSTG   = 3;
constexpr int NCHUNK = DIM / 64;                    // 8
constexpr int GEMM_SMEM = NSTG * ST_B;              // 110592 bytes
}

template <int MODE>
__global__ __launch_bounds__(256, 2) void gemm_fp16(const __half* __restrict__ A,
                                                    const __half* __restrict__ Bm,
                                                    const float* __restrict__ bias,
                                                    float* __restrict__ Cout) {
    extern __shared__ char smc[];
    const int tid = threadIdx.x;
    const int lane = tid & 31, wid = tid >> 5;
    const int g = lane >> 2, t = lane & 3;
    const int m0 = blockIdx.y * 128, n0 = blockIdx.x * 128;
    const int wm = (wid >> 2) * 64, wn = (wid & 3) * 32;
    const uint32_t sb = (uint32_t)__cvta_generic_to_shared(smc);

    const uint32_t laneA = (uint32_t)((((lane >> 3) & 1) * 8 + (lane & 7)) * 144
                                      + (lane >> 4) * 16);
    const uint32_t laneB = (uint32_t)((((lane >> 4) & 1) * 8 + (lane & 7)) * 144
                                      + ((lane >> 3) & 1) * 16);

    float acc[4][4][4];
#pragma unroll
    for (int i = 0; i < 4; ++i)
#pragma unroll
        for (int j = 0; j < 4; ++j)
#pragma unroll
            for (int e = 0; e < 4; ++e) acc[i][j][e] = 0.f;

    auto issue = [&](int c) {
        if (c < NCHUNK) {
            const int st = c % NSTG;
            const int k0 = c * 64;
            char* As = smc + st * ST_B;
            char* Bs = As + 128 * 144;
#pragma unroll
            for (int it = 0; it < 4; ++it) {
                int v = tid + it * 256;
                int row = v >> 3, c8 = (v & 7) * 8;        // halves
                int gm = m0 + row; if (gm > MROWS - 1) gm = MROWS - 1;
                cp16(As + row * 144 + c8 * 2, A + (size_t)gm * DIM + k0 + c8);
                int gn = n0 + row;
                cp16(Bs + row * 144 + c8 * 2, Bm + (size_t)gn * DIM + k0 + c8);
            }
        }
        cp_commit();
    };

    issue(0); issue(1);
    for (int c = 0; c < NCHUNK; ++c) {
        cp_wait<1>();
        __syncthreads();
        issue(c + 2);

        const int st = c % NSTG;
        const uint32_t aAddr = sb + st * ST_B + wm * 144 + laneA;
        const uint32_t bAddr = sb + st * ST_B + 128 * 144 + wn * 144 + laneB;
#pragma unroll
        for (int ks = 0; ks < 4; ++ks) {
            const uint32_t kd = ks * 32;
            uint32_t aR[4][4];
#pragma unroll
            for (int mf = 0; mf < 4; ++mf)
                ldsm4(aR[mf], aAddr + mf * (16 * 144) + kd);
            uint32_t bR[2][4];
#pragma unroll
            for (int p = 0; p < 2; ++p)
                ldsm4(bR[p], bAddr + p * (16 * 144) + kd);
#pragma unroll
            for (int p = 0; p < 2; ++p)
#pragma unroll
                for (int s = 0; s < 2; ++s) {
                    const int nf = p * 2 + s;
#pragma unroll
                    for (int mf = 0; mf < 4; ++mf)
                        mma16(acc[mf][nf], aR[mf], &bR[p][2 * s]);
                }
        }
    }
    __syncthreads();

    if (MODE == 0) {
        if (n0 >= 1024) {
            // ---- V block: transpose 128x128 via smem, coalesced g_vth ----
            float* Ts = reinterpret_cast<float*>(smc);    // [128][132] f32
#pragma unroll
            for (int mf = 0; mf < 4; ++mf)
#pragma unroll
                for (int ri = 0; ri < 2; ++ri) {
                    int lr = wm + mf * 16 + g + ri * 8;
#pragma unroll
                    for (int nf = 0; nf < 4; ++nf)
#pragma unroll
                        for (int ci = 0; ci < 2; ++ci) {
                            int lc = wn + nf * 8 + t * 2 + ci;
                            Ts[lc * 132 + lr] = acc[mf][nf][ri * 2 + ci];
                        }
                }
            __syncthreads();
#pragma unroll
            for (int cchunk = 0; cchunk < 16; ++cchunk) {
                int lc = cchunk * 8 + wid;
                int gn = n0 + lc;
                int rem = gn & 511;
                int h_ = rem >> 6, dd = rem & 63;
#pragma unroll
                for (int mi = 0; mi < 4; ++mi) {
                    int lr = mi * 32 + lane;
                    int gm = m0 + lr;
                    if (gm < MROWS) {
                        int b_ = gm / NTOK;
                        int n_ = gm - b_ * NTOK;
                        g_vth[(((size_t)(b_ * NH + h_)) * DH + dd) * VP + n_] =
                            __float2half_rn(Ts[lc * 132 + lr]);
                    }
                }
            }
        } else {
            // ---- Q/K blocks: half2 scatter; Q pre-scaled by 0.125 (exact) ----
#pragma unroll
            for (int mf = 0; mf < 4; ++mf) {
#pragma unroll
                for (int ri = 0; ri < 2; ++ri) {
                    int gm = m0 + wm + mf * 16 + g + ri * 8;
                    if (gm >= MROWS) continue;
                    int b_ = gm / NTOK;
                    int n_ = gm - b_ * NTOK;
#pragma unroll
                    for (int nf = 0; nf < 4; ++nf) {
                        int gn = n0 + wn + nf * 8 + t * 2;
                        int part = gn >> 9;
                        int rem = gn & 511;
                        int h_ = rem >> 6;
                        int dd = rem & 63;
                        float s = (part == 0) ? 0.125f : 1.f;
                        __half2 hv = __floats2half2_rn(acc[mf][nf][ri * 2] * s,
                                                       acc[mf][nf][ri * 2 + 1] * s);
                        __half* dst = (part == 0) ? g_qh : g_kh;
                        *reinterpret_cast<__half2*>(
                            dst + ((size_t)(b_ * NH + h_) * NTOK + n_) * DH + dd) = hv;
                    }
                }
            }
        }
    } else {
#pragma unroll
        for (int mf = 0; mf < 4; ++mf) {
#pragma unroll
            for (int ri = 0; ri < 2; ++ri) {
                int gm = m0 + wm + mf * 16 + g + ri * 8;
                if (gm >= MROWS) continue;
#pragma unroll
                for (int nf = 0; nf < 4; ++nf) {
                    int cbase = n0 + wn + nf * 8 + t * 2;
                    float2 o;
                    o.x = acc[mf][nf][ri * 2 + 0] + bias[cbase];
                    o.y = acc[mf][nf][ri * 2 + 1] + bias[cbase + 1];
                    *reinterpret_cast<float2*>(Cout + (size_t)gm * DIM + cbase) = o;
                }
            }
        }
    }
}

// ---------------------------------------------------------------------------
// Fused flash attention, fp16 operands. 256 thr / 128 q-rows, 64-key tiles,
// 2 blocks/SM. 3-stage ring: ONE sync per kt. Bias S-init via ldmatrix.
// Smem: Ks[3][64][72]h + Vt[3][64][72]h + Bb[3][128][72]bf16 = 110592 B.
// ---------------------------------------------------------------------------
namespace {
constexpr int KSB = 0;                          // bytes
constexpr int VSB = KSB + 3 * 64 * 144;         // 27648
constexpr int BBB = VSB + 3 * 64 * 144;         // 55296
constexpr int FL_SMEM = BBB + 3 * 128 * 144;    // 110592 bytes
constexpr int NKT = 10;                         // key tiles
}

__global__ __launch_bounds__(256, 2) void flash_attn() {
    extern __shared__ char smc[];
    const uint32_t sb = (uint32_t)__cvta_generic_to_shared(smc);

    const int bh = blockIdx.y, qt = blockIdx.x;
    const int tid = threadIdx.x;
    const int wid = tid >> 5, lane = tid & 31;
    const int g = lane >> 2, t = lane & 3;
    const __half* qb = g_qh + (size_t)bh * NTOK * DH;
    const __half* kb = g_kh + (size_t)bh * NTOK * DH;
    const __half* vtb = g_vth + (size_t)bh * DH * VP;
    const __nv_bfloat16* bp = g_biasph + (size_t)(bh & 7) * NTOK * BPAD;

    const uint32_t laneB = (uint32_t)((((lane >> 4) & 1) * 8 + (lane & 7)) * 144
                                      + ((lane >> 3) & 1) * 16);
    // bias ldmatrix lane offset: rows (lane&7)+8*((lane>>3)&1), col-half (lane>>4)*8
    const uint32_t laneBias = (uint32_t)((((lane >> 3) & 1) * 8 + (lane & 7)) * 144
                                         + (lane >> 4) * 16);

    auto issueTile = [&](int kt) {
        if (kt < NKT) {
            const int st = kt % 3;
            const int k0 = kt * 64;
            char* Ks = smc + KSB + st * (64 * 144);
            char* Vt = smc + VSB + st * (64 * 144);
            char* Bs = smc + BBB + st * (128 * 144);
#pragma unroll
            for (int it = 0; it < 4; ++it) {        // bias: 128 rows x 8 chunks
                int v = tid + it * 256;
                int row = v >> 3, c8 = (v & 7) * 8;
                int gq = qt * 128 + row; if (gq > NTOK - 1) gq = NTOK - 1;
                cp16(Bs + row * 144 + c8 * 2, bp + (size_t)gq * BPAD + k0 + c8);
            }
#pragma unroll
            for (int it = 0; it < 2; ++it) {        // K: 64 rows x 8 chunks
                int v = tid + it * 256;
                int row = v >> 3, c8 = (v & 7) * 8;
                int gk = k0 + row; if (gk > NTOK - 1) gk = NTOK - 1;
                cp16(Ks + row * 144 + c8 * 2, kb + (size_t)gk * DH + c8);
            }
#pragma unroll
            for (int it = 0; it < 2; ++it) {        // V^T: 64 d-rows x 8 chunks
                int v = tid + it * 256;
                int row = v >> 3, c8 = (v & 7) * 8;
                cp16(Vt + row * 144 + c8 * 2, vtb + (size_t)row * VP + k0 + c8);
            }
        }
        cp_commit();
    };

    issueTile(0); issueTile(1);

    const int q0 = wid * 16;
    const int rowA = qt * 128 + q0 + g;
    const int rowB = rowA + 8;

    const __half2* qA = reinterpret_cast<const __half2*>(
        qb + (size_t)min(rowA, NTOK - 1) * DH);
    const __half2* qB = reinterpret_cast<const __half2*>(
        qb + (size_t)min(rowB, NTOK - 1) * DH);
    uint32_t qf[4][4];
#pragma unroll
    for (int ks = 0; ks < 4; ++ks) {
        qf[ks][0] = *reinterpret_cast<const uint32_t*>(qA + ks * 8 + t);
        qf[ks][1] = *reinterpret_cast<const uint32_t*>(qB + ks * 8 + t);
        qf[ks][2] = *reinterpret_cast<const uint32_t*>(qA + ks * 8 + t + 4);
        qf[ks][3] = *reinterpret_cast<const uint32_t*>(qB + ks * 8 + t + 4);
    }

    float accO[8][4];
#pragma unroll
    for (int df = 0; df < 8; ++df)
#pragma unroll
        for (int e = 0; e < 4; ++e) accO[df][e] = 0.f;
    float m_a = -1e30f, m_b = -1e30f, sum_a = 0.f, sum_b = 0.f;

    for (int kt = 0; kt < NKT; ++kt) {
        const int st = kt % 3;
        const uint32_t ksAddr = sb + KSB + st * (64 * 144) + laneB;
        const uint32_t vtAddr = sb + VSB + st * (64 * 144) + laneB;
        const uint32_t bsAddr = sb + BBB + st * (128 * 144) + q0 * 144 + laneBias;

        cp_wait<1>();          // tile kt resident (at most kt+1 pending)
        __syncthreads();       // all warps done reading tile kt-1's stage
        issueTile(kt + 2);     // overwrites stage of tile kt-1 — safe

        // S initialized with bias via ldmatrix (bf16x2 -> f32); mma on top.
        float S[8][4];
#pragma unroll
        for (int p = 0; p < 4; ++p) {
            uint32_t br[4];
            ldsm4(br, bsAddr + p * 32);
            float2 f;
            f = __bfloat1622float2(*reinterpret_cast<__nv_bfloat162*>(&br[0]));
            S[2 * p][0] = f.x; S[2 * p][1] = f.y;
            f = __bfloat1622float2(*reinterpret_cast<__nv_bfloat162*>(&br[1]));
            S[2 * p][2] = f.x; S[2 * p][3] = f.y;
            f = __bfloat1622float2(*reinterpret_cast<__nv_bfloat162*>(&br[2]));
            S[2 * p + 1][0] = f.x; S[2 * p + 1][1] = f.y;
            f = __bfloat1622float2(*reinterpret_cast<__nv_bfloat162*>(&br[3]));
            S[2 * p + 1][2] = f.x; S[2 * p + 1][3] = f.y;
        }
#pragma unroll
        for (int ks = 0; ks < 4; ++ks) {
            const uint32_t kd = ks * 32;
#pragma unroll
            for (int p = 0; p < 4; ++p) {
                uint32_t bR[4];
                ldsm4(bR, ksAddr + p * (16 * 144) + kd);
                mma16(S[p * 2 + 0], qf[ks], &bR[0]);
                mma16(S[p * 2 + 1], qf[ks], &bR[2]);
            }
        }

        // online softmax (Q pre-scaled: S is already the full logit)
        float ma = -1e30f, mb = -1e30f;
#pragma unroll
        for (int nf = 0; nf < 8; ++nf) {
            ma = fmaxf(ma, fmaxf(S[nf][0], S[nf][1]));
            mb = fmaxf(mb, fmaxf(S[nf][2], S[nf][3]));
        }
        ma = fmaxf(ma, __shfl_xor_sync(0xFFFFFFFFu, ma, 1));
        ma = fmaxf(ma, __shfl_xor_sync(0xFFFFFFFFu, ma, 2));
        mb = fmaxf(mb, __shfl_xor_sync(0xFFFFFFFFu, mb, 1));
        mb = fmaxf(mb, __shfl_xor_sync(0xFFFFFFFFu, mb, 2));

        float mna = fmaxf(m_a, ma), mnb = fmaxf(m_b, mb);
        float alA = exp2f((m_a - mna) * LOG2E);
        float alB = exp2f((m_b - mnb) * LOG2E);
        m_a = mna; m_b = mnb;

        // P = 2^((S-m)*log2e) computed in f16x2 (ex2.approx.f16x2)
        uint32_t Sp[8][2];
        float pa = 0.f, pb = 0.f;
#pragma unroll
        for (int nf = 0; nf < 8; ++nf) {
            __half2 e0 = h2exp2(__floats2half2_rn((S[nf][0] - mna) * LOG2E,
                                                  (S[nf][1] - mna) * LOG2E));
            __half2 e1 = h2exp2(__floats2half2_rn((S[nf][2] - mnb) * LOG2E,
                                                  (S[nf][3] - mnb) * LOG2E));
            Sp[nf][0] = *reinterpret_cast<uint32_t*>(&e0);
            Sp[nf][1] = *reinterpret_cast<uint32_t*>(&e1);
            float2 f0 = __half22float2(e0);
            float2 f1 = __half22float2(e1);
            pa += f0.x + f0.y;
            pb += f1.x + f1.y;
        }
        sum_a = sum_a * alA + pa;
        sum_b = sum_b * alB + pb;
#pragma unroll
        for (int df = 0; df < 8; ++df) {
            accO[df][0] *= alA; accO[df][1] *= alA;
            accO[df][2] *= alB; accO[df][3] *= alB;
        }

        // O += P V : a-fragments from packed P, b from V^T ldmatrix
#pragma unroll
        for (int ks = 0; ks < 4; ++ks) {
            uint32_t a[4];
            a[0] = Sp[2 * ks][0];
            a[1] = Sp[2 * ks][1];
            a[2] = Sp[2 * ks + 1][0];
            a[3] = Sp[2 * ks + 1][1];
            const uint32_t kd = ks * 32;
#pragma unroll
            for (int p = 0; p < 4; ++p) {
                uint32_t bR[4];
                ldsm4(bR, vtAddr + p * (16 * 144) + kd);
                mma16(accO[p * 2 + 0], a, &bR[0]);
                mma16(accO[p * 2 + 1], a, &bR[2]);
            }
        }
    }

    sum_a += __shfl_xor_sync(0xFFFFFFFFu, sum_a, 1);
    sum_a += __shfl_xor_sync(0xFFFFFFFFu, sum_a, 2);
    sum_b += __shfl_xor_sync(0xFFFFFFFFu, sum_b, 1);
    sum_b += __shfl_xor_sync(0xFFFFFFFFu, sum_b, 2);
    const float ia = 1.f / sum_a, ib = 1.f / sum_b;

    const int b_ = bh >> 3, h_ = bh & 7;
#pragma unroll
    for (int df = 0; df < 8; ++df) {
        int col = h_ * 64 + df * 8 + t * 2;
        if (rowA < NTOK) {
            __half2 o = __floats2half2_rn(accO[df][0] * ia, accO[df][1] * ia);
            *reinterpret_cast<__half2*>(
                g_attnh + (size_t)(b_ * NTOK + rowA) * DIM + col) = o;
        }
        if (rowB < NTOK) {
            __half2 o = __floats2half2_rn(accO[df][2] * ib, accO[df][3] * ib);
            *reinterpret_cast<__half2*>(
                g_attnh + (size_t)(b_ * NTOK + rowB) * DIM + col) = o;
        }
    }
}

// ---------------------------------------------------------------------------
extern "C" void kernel_launch(void* const* d_in, const int* in_sizes, int n_in,
                              void* d_out, int out_size) {
    (void)in_sizes; (void)n_in; (void)out_size;
    const float* x          = (const float*)d_in[0];
    const float* qkv_w      = (const float*)d_in[1];
    const float* proj_w     = (const float*)d_in[2];
    const float* proj_b     = (const float*)d_in[3];
    const float* bias_table = (const float*)d_in[4];
    const int*   rel_index  = (const int*)d_in[5];
    float* out = (float*)d_out;

    static bool attr_done = false;
    if (!attr_done) {
        cudaFuncSetAttribute(gemm_fp16<0>, cudaFuncAttributeMaxDynamicSharedMemorySize, GEMM_SMEM);
        cudaFuncSetAttribute(gemm_fp16<1>, cudaFuncAttributeMaxDynamicSharedMemorySize, GEMM_SMEM);
        cudaFuncSetAttribute(flash_attn, cudaFuncAttributeMaxDynamicSharedMemorySize, FL_SMEM);
        attr_done = true;
    }

    __half *xh = nullptr, *wqh = nullptr, *wph = nullptr, *ath = nullptr;
    cudaGetSymbolAddress((void**)&xh, g_xh);
    cudaGetSymbolAddress((void**)&wqh, g_wqh);
    cudaGetSymbolAddress((void**)&wph, g_wph);
    cudaGetSymbolAddress((void**)&ath, g_attnh);

    prep_all<<<(N_PREP + 255) / 256, 256>>>(
        (const float4*)x, (const float4*)qkv_w, (const float4*)proj_w,
        bias_table, rel_index);

    gemm_fp16<0><<<dim3(12, 145), 256, GEMM_SMEM>>>(xh, wqh, nullptr, nullptr);
    flash_attn<<<dim3(5, BH), 256, FL_SMEM>>>();
    gemm_fp16<1><<<dim3(4, 145), 256, GEMM_SMEM>>>(ath, wph, proj_b, out);
}

// round 17
// speedup vs baseline: 1.0213x; 1.0062x over previous
#include <cuda_runtime.h>
#include <cuda_fp16.h>
#include <cuda_bf16.h>
#include <cstdint>

// ---------------------------------------------------------------------------
// Relative attention — fp16 mma.sync m16n8k16 + ldmatrix. Round 16:
//  * GEMMs reverted to round-14 config (256 thr, 64x32 warp tiles, 2 blk/SM)
//  * flash: 3-stage ring (ONE sync per kt) + bias S-init via ldmatrix
// ---------------------------------------------------------------------------

namespace {
constexpr int BATCH = 32;
constexpr int NH    = 8;
constexpr int NTOK  = 577;
constexpr int DIM   = 512;
constexpr int DH    = 64;
constexpr int BH    = BATCH * NH;        // 256
constexpr int MROWS = BATCH * NTOK;      // 18464
constexpr int BPAD  = 640;               // padded bias row stride (bf16)
constexpr int VP    = 640;               // padded V^T row stride (tokens)
constexpr float LOG2E = 1.4426950408889634f;
}

// Scratch (device globals: allocation-free contract; zero-initialized)
__device__ __half g_xh[MROWS * DIM];                   // fp16 x
__device__ __half g_wqh[3 * DIM * DIM];                // fp16 qkv_w
__device__ __half g_wph[DIM * DIM];                    // fp16 proj_w
__device__ __half g_qh[BH * NTOK * DH];                // fp16 Q (pre-scaled x0.125)
__device__ __half g_kh[BH * NTOK * DH];                // fp16 K
__device__ __half g_vth[BH * DH * VP];                 // fp16 V^T, pads stay 0
__device__ __nv_bfloat16 g_biasph[NH * NTOK * BPAD];   // bf16 bias, pad=-1e30
__device__ __half g_attnh[MROWS * DIM];                // fp16 attention out

// ---------------------------------------------------------------------------
__device__ __forceinline__ void mma16(float* d, const uint32_t* a, const uint32_t* b) {
    asm volatile(
        "mma.sync.aligned.m16n8k16.row.col.f32.f16.f16.f32 "
        "{%0,%1,%2,%3},{%4,%5,%6,%7},{%8,%9},{%0,%1,%2,%3};"
        : "+f"(d[0]), "+f"(d[1]), "+f"(d[2]), "+f"(d[3])
        : "r"(a[0]), "r"(a[1]), "r"(a[2]), "r"(a[3]),
          "r"(b[0]), "r"(b[1]));
}

__device__ __forceinline__ void ldsm4(uint32_t* r, uint32_t addr) {
    asm volatile("ldmatrix.sync.aligned.m8n8.x4.shared.b16 {%0,%1,%2,%3}, [%4];"
                 : "=r"(r[0]), "=r"(r[1]), "=r"(r[2]), "=r"(r[3]) : "r"(addr));
}

__device__ __forceinline__ void cp16(void* dst, const void* src) {
    unsigned d = (unsigned)__cvta_generic_to_shared(dst);
    asm volatile("cp.async.cg.shared.global [%0], [%1], 16;\n" :: "r"(d), "l"(src));
}
__device__ __forceinline__ void cp_commit() {
    asm volatile("cp.async.commit_group;\n" ::);
}
template <int N>
__device__ __forceinline__ void cp_wait() {
    asm volatile("cp.async.wait_group %0;\n" :: "n"(N));
}

// ---------------------------------------------------------------------------
// Fused prep: fp16-convert x, qkv_w, proj_w (8 floats/thread); expand bias.
// ---------------------------------------------------------------------------
namespace {
constexpr int N_XH = MROWS * DIM / 8;        // 1181696
constexpr int N_WQ = 3 * DIM * DIM / 8;      // 98304
constexpr int N_WP = DIM * DIM / 8;          // 32768
constexpr int N_B  = NTOK * BPAD;            // 369280
constexpr int N_PREP = N_XH + N_WQ + N_WP + N_B;
}

__device__ __forceinline__ void cvt8(__half* dst, const float4* src, int i) {
    float4 a = src[2 * i], b = src[2 * i + 1];
    __half2* d2 = reinterpret_cast<__half2*>(dst + 8 * i);
    d2[0] = __floats2half2_rn(a.x, a.y);
    d2[1] = __floats2half2_rn(a.z, a.w);
    d2[2] = __floats2half2_rn(b.x, b.y);
    d2[3] = __floats2half2_rn(b.z, b.w);
}

__global__ void prep_all(const float4* __restrict__ x,
                         const float4* __restrict__ wq,
                         const float4* __restrict__ wp,
                         const float* __restrict__ table,
                         const int* __restrict__ rel) {
    int i = blockIdx.x * 256 + threadIdx.x;
    if (i < N_XH) { cvt8(g_xh, x, i); return; }
    i -= N_XH;
    if (i < N_WQ) { cvt8(g_wqh, wq, i); return; }
    i -= N_WQ;
    if (i < N_WP) { cvt8(g_wph, wp, i); return; }
    i -= N_WP;
    if (i < N_B) {
        int n = i / BPAD, c = i - n * BPAD;
        if (c < NTOK) {
            int r = rel[n * NTOK + c];
#pragma unroll
            for (int h = 0; h < NH; ++h)
                g_biasph[((size_t)h * NTOK + n) * BPAD + c] =
                    __float2bfloat16_rn(table[r * NH + h]);
        } else {
            __nv_bfloat16 neg = __float2bfloat16_rn(-1e30f);
#pragma unroll
            for (int h = 0; h < NH; ++h)
                g_biasph[((size_t)h * NTOK + n) * BPAD + c] = neg;
        }
    }
}

// ---------------------------------------------------------------------------
// fp16 NT GEMM (round-14 config). Block 128x128, 8 warps, 64x32 warp tiles,
// 64-K chunks, 3-stage cp.async ring, one sync/iter, 2 blocks/SM.
// Rows padded to 72 halves (144 B). MODE 0: q(x0.125)/k scatter + V smem
// transpose -> g_vth.  MODE 1: f32 acc + bias -> Cout.
// ---------------------------------------------------------------------------
namespace {
constexpr int ST_B   = 2 * 128 * 144;               // bytes per stage (A+B)
constexpr int NSTG   = 3;
constexpr int NCHUNK = DIM / 64;                    // 8
constexpr int GEMM_SMEM = NSTG * ST_B;              // 110592 bytes
}

template <int MODE>
__global__ __launch_bounds__(256, 2) void gemm_fp16(const __half* __restrict__ A,
                                                    const __half* __restrict__ Bm,
                                                    const float* __restrict__ bias,
                                                    float* __restrict__ Cout) {
    extern __shared__ char smc[];
    const int tid = threadIdx.x;
    const int lane = tid & 31, wid = tid >> 5;
    const int g = lane >> 2, t = lane & 3;
    const int m0 = blockIdx.y * 128, n0 = blockIdx.x * 128;
    const int wm = (wid >> 2) * 64, wn = (wid & 3) * 32;
    const uint32_t sb = (uint32_t)__cvta_generic_to_shared(smc);

    const uint32_t laneA = (uint32_t)((((lane >> 3) & 1) * 8 + (lane & 7)) * 144
                                      + (lane >> 4) * 16);
    const uint32_t laneB = (uint32_t)((((lane >> 4) & 1) * 8 + (lane & 7)) * 144
                                      + ((lane >> 3) & 1) * 16);

    float acc[4][4][4];
#pragma unroll
    for (int i = 0; i < 4; ++i)
#pragma unroll
        for (int j = 0; j < 4; ++j)
#pragma unroll
            for (int e = 0; e < 4; ++e) acc[i][j][e] = 0.f;

    auto issue = [&](int c) {
        if (c < NCHUNK) {
            const int st = c % NSTG;
            const int k0 = c * 64;
            char* As = smc + st * ST_B;
            char* Bs = As + 128 * 144;
#pragma unroll
            for (int it = 0; it < 4; ++it) {
                int v = tid + it * 256;
                int row = v >> 3, c8 = (v & 7) * 8;        // halves
                int gm = m0 + row; if (gm > MROWS - 1) gm = MROWS - 1;
                cp16(As + row * 144 + c8 * 2, A + (size_t)gm * DIM + k0 + c8);
                int gn = n0 + row;
                cp16(Bs + row * 144 + c8 * 2, Bm + (size_t)gn * DIM + k0 + c8);
            }
        }
        cp_commit();
    };

    issue(0); issue(1);
    for (int c = 0; c < NCHUNK; ++c) {
        cp_wait<1>();
        __syncthreads();
        issue(c + 2);

        const int st = c % NSTG;
        const uint32_t aAddr = sb + st * ST_B + wm * 144 + laneA;
        const uint32_t bAddr = sb + st * ST_B + 128 * 144 + wn * 144 + laneB;
#pragma unroll
        for (int ks = 0; ks < 4; ++ks) {
            const uint32_t kd = ks * 32;
            uint32_t aR[4][4];
#pragma unroll
            for (int mf = 0; mf < 4; ++mf)
                ldsm4(aR[mf], aAddr + mf * (16 * 144) + kd);
            uint32_t bR[2][4];
#pragma unroll
            for (int p = 0; p < 2; ++p)
                ldsm4(bR[p], bAddr + p * (16 * 144) + kd);
#pragma unroll
            for (int p = 0; p < 2; ++p)
#pragma unroll
                for (int s = 0; s < 2; ++s) {
                    const int nf = p * 2 + s;
#pragma unroll
                    for (int mf = 0; mf < 4; ++mf)
                        mma16(acc[mf][nf], aR[mf], &bR[p][2 * s]);
                }
        }
    }
    __syncthreads();

    if (MODE == 0) {
        if (n0 >= 1024) {
            // ---- V block: transpose 128x128 via smem, coalesced g_vth ----
            float* Ts = reinterpret_cast<float*>(smc);    // [128][132] f32
#pragma unroll
            for (int mf = 0; mf < 4; ++mf)
#pragma unroll
                for (int ri = 0; ri < 2; ++ri) {
                    int lr = wm + mf * 16 + g + ri * 8;
#pragma unroll
                    for (int nf = 0; nf < 4; ++nf)
#pragma unroll
                        for (int ci = 0; ci < 2; ++ci) {
                            int lc = wn + nf * 8 + t * 2 + ci;
                            Ts[lc * 132 + lr] = acc[mf][nf][ri * 2 + ci];
                        }
                }
            __syncthreads();
#pragma unroll
            for (int cchunk = 0; cchunk < 16; ++cchunk) {
                int lc = cchunk * 8 + wid;
                int gn = n0 + lc;
                int rem = gn & 511;
                int h_ = rem >> 6, dd = rem & 63;
#pragma unroll
                for (int mi = 0; mi < 4; ++mi) {
                    int lr = mi * 32 + lane;
                    int gm = m0 + lr;
                    if (gm < MROWS) {
                        int b_ = gm / NTOK;
                        int n_ = gm - b_ * NTOK;
                        g_vth[(((size_t)(b_ * NH + h_)) * DH + dd) * VP + n_] =
                            __float2half_rn(Ts[lc * 132 + lr]);
                    }
                }
            }
        } else {
            // ---- Q/K blocks: half2 scatter; Q pre-scaled by 0.125 (exact) ----
#pragma unroll
            for (int mf = 0; mf < 4; ++mf) {
#pragma unroll
                for (int ri = 0; ri < 2; ++ri) {
                    int gm = m0 + wm + mf * 16 + g + ri * 8;
                    if (gm >= MROWS) continue;
                    int b_ = gm / NTOK;
                    int n_ = gm - b_ * NTOK;
#pragma unroll
                    for (int nf = 0; nf < 4; ++nf) {
                        int gn = n0 + wn + nf * 8 + t * 2;
                        int part = gn >> 9;
                        int rem = gn & 511;
                        int h_ = rem >> 6;
                        int dd = rem & 63;
                        float s = (part == 0) ? 0.125f : 1.f;
                        __half2 hv = __floats2half2_rn(acc[mf][nf][ri * 2] * s,
                                                       acc[mf][nf][ri * 2 + 1] * s);
                        __half* dst = (part == 0) ? g_qh : g_kh;
                        *reinterpret_cast<__half2*>(
                            dst + ((size_t)(b_ * NH + h_) * NTOK + n_) * DH + dd) = hv;
                    }
                }
            }
        }
    } else {
#pragma unroll
        for (int mf = 0; mf < 4; ++mf) {
#pragma unroll
            for (int ri = 0; ri < 2; ++ri) {
                int gm = m0 + wm + mf * 16 + g + ri * 8;
                if (gm >= MROWS) continue;
#pragma unroll
                for (int nf = 0; nf < 4; ++nf) {
                    int cbase = n0 + wn + nf * 8 + t * 2;
                    float2 o;
                    o.x = acc[mf][nf][ri * 2 + 0] + bias[cbase];
                    o.y = acc[mf][nf][ri * 2 + 1] + bias[cbase + 1];
                    *reinterpret_cast<float2*>(Cout + (size_t)gm * DIM + cbase) = o;
                }
            }
        }
    }
}

// ---------------------------------------------------------------------------
// Fused flash attention, fp16 operands. 256 thr / 128 q-rows, 64-key tiles,
// 2 blocks/SM. 3-stage ring: ONE sync per kt. Bias S-init via ldmatrix.
// Smem: Ks[3][64][72]h + Vt[3][64][72]h + Bb[3][128][72]bf16 = 110592 B.
// ---------------------------------------------------------------------------
namespace {
constexpr int KSB = 0;                          // bytes
constexpr int VSB = KSB + 3 * 64 * 144;         // 27648
constexpr int BBB = VSB + 3 * 64 * 144;         // 55296
constexpr int FL_SMEM = BBB + 3 * 128 * 144;    // 110592 bytes
constexpr int NKT = 10;                         // key tiles
}

__global__ __launch_bounds__(256, 2) void flash_attn() {
    extern __shared__ char smc[];
    const uint32_t sb = (uint32_t)__cvta_generic_to_shared(smc);

    const int bh = blockIdx.y, qt = blockIdx.x;
    const int tid = threadIdx.x;
    const int wid = tid >> 5, lane = tid & 31;
    const int g = lane >> 2, t = lane & 3;
    const __half* qb = g_qh + (size_t)bh * NTOK * DH;
    const __half* kb = g_kh + (size_t)bh * NTOK * DH;
    const __half* vtb = g_vth + (size_t)bh * DH * VP;
    const __nv_bfloat16* bp = g_biasph + (size_t)(bh & 7) * NTOK * BPAD;

    const uint32_t laneB = (uint32_t)((((lane >> 4) & 1) * 8 + (lane & 7)) * 144
                                      + ((lane >> 3) & 1) * 16);
    // bias ldmatrix lane offset: rows (lane&7)+8*((lane>>3)&1), col-half (lane>>4)*8
    const uint32_t laneBias = (uint32_t)((((lane >> 3) & 1) * 8 + (lane & 7)) * 144
                                         + (lane >> 4) * 16);

    auto issueTile = [&](int kt) {
        if (kt < NKT) {
            const int st = kt % 3;
            const int k0 = kt * 64;
            char* Ks = smc + KSB + st * (64 * 144);
            char* Vt = smc + VSB + st * (64 * 144);
            char* Bs = smc + BBB + st * (128 * 144);
#pragma unroll
            for (int it = 0; it < 4; ++it) {        // bias: 128 rows x 8 chunks
                int v = tid + it * 256;
                int row = v >> 3, c8 = (v & 7) * 8;
                int gq = qt * 128 + row; if (gq > NTOK - 1) gq = NTOK - 1;
                cp16(Bs + row * 144 + c8 * 2, bp + (size_t)gq * BPAD + k0 + c8);
            }
#pragma unroll
            for (int it = 0; it < 2; ++it) {        // K: 64 rows x 8 chunks
                int v = tid + it * 256;
                int row = v >> 3, c8 = (v & 7) * 8;
                int gk = k0 + row; if (gk > NTOK - 1) gk = NTOK - 1;
                cp16(Ks + row * 144 + c8 * 2, kb + (size_t)gk * DH + c8);
            }
#pragma unroll
            for (int it = 0; it < 2; ++it) {        // V^T: 64 d-rows x 8 chunks
                int v = tid + it * 256;
                int row = v >> 3, c8 = (v & 7) * 8;
                cp16(Vt + row * 144 + c8 * 2, vtb + (size_t)row * VP + k0 + c8);
            }
        }
        cp_commit();
    };

    issueTile(0); issueTile(1);

    const int q0 = wid * 16;
    const int rowA = qt * 128 + q0 + g;
    const int rowB = rowA + 8;

    const __half2* qA = reinterpret_cast<const __half2*>(
        qb + (size_t)min(rowA, NTOK - 1) * DH);
    const __half2* qB = reinterpret_cast<const __half2*>(
        qb + (size_t)min(rowB, NTOK - 1) * DH);
    uint32_t qf[4][4];
#pragma unroll
    for (int ks = 0; ks < 4; ++ks) {
        qf[ks][0] = *reinterpret_cast<const uint32_t*>(qA + ks * 8 + t);
        qf[ks][1] = *reinterpret_cast<const uint32_t*>(qB + ks * 8 + t);
        qf[ks][2] = *reinterpret_cast<const uint32_t*>(qA + ks * 8 + t + 4);
        qf[ks][3] = *reinterpret_cast<const uint32_t*>(qB + ks * 8 + t + 4);
    }

    float accO[8][4];
#pragma unroll
    for (int df = 0; df < 8; ++df)
#pragma unroll
        for (int e = 0; e < 4; ++e) accO[df][e] = 0.f;
    float m_a = -1e30f, m_b = -1e30f, sum_a = 0.f, sum_b = 0.f;

    for (int kt = 0; kt < NKT; ++kt) {
        const int st = kt % 3;
        const uint32_t ksAddr = sb + KSB + st * (64 * 144) + laneB;
        const uint32_t vtAddr = sb + VSB + st * (64 * 144) + laneB;
        const uint32_t bsAddr = sb + BBB + st * (128 * 144) + q0 * 144 + laneBias;

        cp_wait<1>();          // tile kt resident (at most kt+1 pending)
        __syncthreads();       // all warps done reading tile kt-1's stage
        issueTile(kt + 2);     // overwrites stage of tile kt-1 — safe

        // S initialized with bias via ldmatrix (bf16x2 -> f32); mma on top.
        float S[8][4];
#pragma unroll
        for (int p = 0; p < 4; ++p) {
            uint32_t br[4];
            ldsm4(br, bsAddr + p * 32);
            float2 f;
            f = __bfloat1622float2(*reinterpret_cast<__nv_bfloat162*>(&br[0]));
            S[2 * p][0] = f.x; S[2 * p][1] = f.y;
            f = __bfloat1622float2(*reinterpret_cast<__nv_bfloat162*>(&br[1]));
            S[2 * p][2] = f.x; S[2 * p][3] = f.y;
            f = __bfloat1622float2(*reinterpret_cast<__nv_bfloat162*>(&br[2]));
            S[2 * p + 1][0] = f.x; S[2 * p + 1][1] = f.y;
            f = __bfloat1622float2(*reinterpret_cast<__nv_bfloat162*>(&br[3]));
            S[2 * p + 1][2] = f.x; S[2 * p + 1][3] = f.y;
        }
#pragma unroll
        for (int ks = 0; ks < 4; ++ks) {
            const uint32_t kd = ks * 32;
#pragma unroll
            for (int p = 0; p < 4; ++p) {
                uint32_t bR[4];
                ldsm4(bR, ksAddr + p * (16 * 144) + kd);
                mma16(S[p * 2 + 0], qf[ks], &bR[0]);
                mma16(S[p * 2 + 1], qf[ks], &bR[2]);
            }
        }

        // online softmax (Q pre-scaled: S is already the full logit)
        float ma = -1e30f, mb = -1e30f;
#pragma unroll
        for (int nf = 0; nf < 8; ++nf) {
            ma = fmaxf(ma, fmaxf(S[nf][0], S[nf][1]));
            mb = fmaxf(mb, fmaxf(S[nf][2], S[nf][3]));
        }
        ma = fmaxf(ma, __shfl_xor_sync(0xFFFFFFFFu, ma, 1));
        ma = fmaxf(ma, __shfl_xor_sync(0xFFFFFFFFu, ma, 2));
        mb = fmaxf(mb, __shfl_xor_sync(0xFFFFFFFFu, mb, 1));
        mb = fmaxf(mb, __shfl_xor_sync(0xFFFFFFFFu, mb, 2));

        float mna = fmaxf(m_a, ma), mnb = fmaxf(m_b, mb);
        float alA = exp2f((m_a - mna) * LOG2E);
        float alB = exp2f((m_b - mnb) * LOG2E);
        m_a = mna; m_b = mnb;

        // P = 2^((S-m)*log2e) computed in f16x2 (ex2.approx.f16x2)
        uint32_t Sp[8][2];
        float pa = 0.f, pb = 0.f;
#pragma unroll
        for (int nf = 0; nf < 8; ++nf) {
            __half2 e0 = h2exp2(__floats2half2_rn((S[nf][0] - mna) * LOG2E,
                                                  (S[nf][1] - mna) * LOG2E));
            __half2 e1 = h2exp2(__floats2half2_rn((S[nf][2] - mnb) * LOG2E,
                                                  (S[nf][3] - mnb) * LOG2E));
            Sp[nf][0] = *reinterpret_cast<uint32_t*>(&e0);
            Sp[nf][1] = *reinterpret_cast<uint32_t*>(&e1);
            float2 f0 = __half22float2(e0);
            float2 f1 = __half22float2(e1);
            pa += f0.x + f0.y;
            pb += f1.x + f1.y;
        }
        sum_a = sum_a * alA + pa;
        sum_b = sum_b * alB + pb;
#pragma unroll
        for (int df = 0; df < 8; ++df) {
            accO[df][0] *= alA; accO[df][1] *= alA;
            accO[df][2] *= alB; accO[df][3] *= alB;
        }

        // O += P V : a-fragments from packed P, b from V^T ldmatrix
#pragma unroll
        for (int ks = 0; ks < 4; ++ks) {
            uint32_t a[4];
            a[0] = Sp[2 * ks][0];
            a[1] = Sp[2 * ks][1];
            a[2] = Sp[2 * ks + 1][0];
            a[3] = Sp[2 * ks + 1][1];
            const uint32_t kd = ks * 32;
#pragma unroll
            for (int p = 0; p < 4; ++p) {
                uint32_t bR[4];
                ldsm4(bR, vtAddr + p * (16 * 144) + kd);
                mma16(accO[p * 2 + 0], a, &bR[0]);
                mma16(accO[p * 2 + 1], a, &bR[2]);
            }
        }
    }

    sum_a += __shfl_xor_sync(0xFFFFFFFFu, sum_a, 1);
    sum_a += __shfl_xor_sync(0xFFFFFFFFu, sum_a, 2);
    sum_b += __shfl_xor_sync(0xFFFFFFFFu, sum_b, 1);
    sum_b += __shfl_xor_sync(0xFFFFFFFFu, sum_b, 2);
    const float ia = 1.f / sum_a, ib = 1.f / sum_b;

    const int b_ = bh >> 3, h_ = bh & 7;
#pragma unroll
    for (int df = 0; df < 8; ++df) {
        int col = h_ * 64 + df * 8 + t * 2;
        if (rowA < NTOK) {
            __half2 o = __floats2half2_rn(accO[df][0] * ia, accO[df][1] * ia);
            *reinterpret_cast<__half2*>(
                g_attnh + (size_t)(b_ * NTOK + rowA) * DIM + col) = o;
        }
        if (rowB < NTOK) {
            __half2 o = __floats2half2_rn(accO[df][2] * ib, accO[df][3] * ib);
            *reinterpret_cast<__half2*>(
                g_attnh + (size_t)(b_ * NTOK + rowB) * DIM + col) = o;
        }
    }
}

// ---------------------------------------------------------------------------
extern "C" void kernel_launch(void* const* d_in, const int* in_sizes, int n_in,
                              void* d_out, int out_size) {
    (void)in_sizes; (void)n_in; (void)out_size;
    const float* x          = (const float*)d_in[0];
    const float* qkv_w      = (const float*)d_in[1];
    const float* proj_w     = (const float*)d_in[2];
    const float* proj_b     = (const float*)d_in[3];
    const float* bias_table = (const float*)d_in[4];
    const int*   rel_index  = (const int*)d_in[5];
    float* out = (float*)d_out;

    static bool attr_done = false;
    if (!attr_done) {
        cudaFuncSetAttribute(gemm_fp16<0>, cudaFuncAttributeMaxDynamicSharedMemorySize, GEMM_SMEM);
        cudaFuncSetAttribute(gemm_fp16<1>, cudaFuncAttributeMaxDynamicSharedMemorySize, GEMM_SMEM);
        cudaFuncSetAttribute(flash_attn, cudaFuncAttributeMaxDynamicSharedMemorySize, FL_SMEM);
        attr_done = true;
    }

    __half *xh = nullptr, *wqh = nullptr, *wph = nullptr, *ath = nullptr;
    cudaGetSymbolAddress((void**)&xh, g_xh);
    cudaGetSymbolAddress((void**)&wqh, g_wqh);
    cudaGetSymbolAddress((void**)&wph, g_wph);
    cudaGetSymbolAddress((void**)&ath, g_attnh);

    prep_all<<<(N_PREP + 255) / 256, 256>>>(
        (const float4*)x, (const float4*)qkv_w, (const float4*)proj_w,
        bias_table, rel_index);

    gemm_fp16<0><<<dim3(12, 145), 256, GEMM_SMEM>>>(xh, wqh, nullptr, nullptr);
    flash_attn<<<dim3(5, BH), 256, FL_SMEM>>>();
    gemm_fp16<1><<<dim3(4, 145), 256, GEMM_SMEM>>>(ath, wph, proj_b, out);
}